// round 9
// baseline (speedup 1.0000x reference)
#include <cuda_runtime.h>
#include <cstdint>

#define BB 64
#define SS 2048
#define II 64
#define HH 128
#define CH 8
#define NCH (SS/CH)
#define MROWS (BB*SS)
#define NHELP 20

typedef unsigned long long ull;

// Scratch + flags (no runtime allocation allowed).
__device__ __align__(256) float g_seq0[(size_t)MROWS * HH];   // layer-0 output
__device__ __align__(256) float g_xw1p[(size_t)MROWS * HH];   // partial xw1 (k<64)
__device__ unsigned g_flagP[BB];
__device__ unsigned g_flagH[BB];

#define BAR_SYNC(id, cnt)   asm volatile("bar.sync %0, %1;"   :: "r"(id), "r"(cnt) : "memory")
#define BAR_ARRIVE(id, cnt) asm volatile("bar.arrive %0, %1;" :: "r"(id), "r"(cnt) : "memory")

// ---------------- packed f32x2 helpers (sm_100+) ----------------
__device__ __forceinline__ ull packf2(float lo, float hi) {
    ull r; asm("mov.b64 %0, {%1, %2};" : "=l"(r) : "f"(lo), "f"(hi)); return r;
}
__device__ __forceinline__ float2 unpackf2(ull v) {
    float2 r; asm("mov.b64 {%0, %1}, %2;" : "=f"(r.x), "=f"(r.y) : "l"(v)); return r;
}
__device__ __forceinline__ ull ffma2(ull a, ull b, ull c) {
    ull d; asm("fma.rn.f32x2 %0, %1, %2, %3;" : "=l"(d) : "l"(a), "l"(b), "l"(c)); return d;
}
__device__ __forceinline__ ull addf2(ull a, ull b) {
    ull d; asm("add.rn.f32x2 %0, %1, %2;" : "=l"(d) : "l"(a), "l"(b)); return d;
}
__device__ __forceinline__ void lds_v2u64(ull &p0, ull &p1, uint32_t addr) {
    asm volatile("ld.shared.v2.u64 {%0, %1}, [%2];" : "=l"(p0), "=l"(p1) : "r"(addr));
}
__device__ __forceinline__ float ex2f(float x) {
    float r; asm("ex2.approx.ftz.f32 %0, %1;" : "=f"(r) : "f"(x)); return r;
}
__device__ __forceinline__ float rcpf(float x) {
    float r; asm("rcp.approx.ftz.f32 %0, %1;" : "=f"(r) : "f"(x)); return r;
}
__device__ __forceinline__ float sigmoidf_(float x) {
    return rcpf(1.0f + ex2f(-1.4426950408889634f * x));
}
__device__ __forceinline__ float tanhf_(float x) {
    float e = ex2f(2.8853900817779268f * x);
    return 1.0f - 2.0f * rcpf(e + 1.0f);
}
__device__ __forceinline__ unsigned ld_acquire(const unsigned* p) {
    unsigned v;
    asm volatile("ld.acquire.gpu.global.u32 %0, [%1];" : "=r"(v) : "l"(p) : "memory");
    return v;
}
__device__ __forceinline__ void st_release(unsigned* p, unsigned v) {
    asm volatile("st.release.gpu.global.u32 [%0], %1;" :: "l"(p), "r"(v) : "memory");
}

__global__ void zero_flags() {
    if (threadIdx.x < BB) { g_flagP[threadIdx.x] = 0; g_flagH[threadIdx.x] = 0; }
}

// ================= P / C role: scan (tid>=256, hi-wid) + proj (tid<256) ==========
// Scan: 2-way k-split, thread (q,c): q=lane>>4, c=warp*16+(lane&15); ureg 32 ull.
// Proj: stages 64 columns of each chunk row (C0 offset into rows of stride STRIDE),
//   2-way split -> 32 values/thread, wreg[16]; consumer additionally adds the
//   helper-provided partial xw1p (ADDP). One bar per step; xw double-buffered.
// Flags: PROD releases g_flagP[b]; consumer gates staging on g_flagH[b] (which
//   transitively implies producer visibility). DAG: P -> H -> C.
template<int STRIDE, int C0, bool PROD>
__device__ __forceinline__ void scan_cta(
    float* hs, float* xt, float* xw_s,
    const float* __restrict__ xsrc,
    const float* __restrict__ u, const float* __restrict__ w,
    const float* bg, const float* bu,
    const float* zeta, const float* nu,
    const float* lambd, const float* gamma,
    const float* __restrict__ xw1p,   // [S,H] partial (consumer) or nullptr
    float* __restrict__ outp, float* __restrict__ hl,
    unsigned* flagRel, const unsigned* flagWait)
{
    constexpr int XROW = 72;          // 2 halves x (32+4) floats
    constexpr int XTS  = CH * XROW;

    const int tid  = threadIdx.x;
    const int lane = tid & 31;

    if (tid >= 256) {
        // ---------------- SCAN (high wids) ----------------
        const int s  = tid - 256;
        const int wp = s >> 5;
        const int q  = lane >> 4;
        const int c  = wp * 16 + (lane & 15);

        ull ureg[32];
#pragma unroll
        for (int m = 0; m < 32; m++) {
            int k0 = 64 * q + 2 * m;
            ureg[m] = packf2(u[(size_t)k0 * HH + c], u[(size_t)(k0 + 1) * HH + c]);
        }
        const float bgj = bg[c], buj = bu[c];
        const float sz = sigmoidf_(zeta[0]);
        const float sn = sigmoidf_(nu[0]);
        float gc = gamma[0];
        gc = fminf(fmaxf(gc, 0.0f), 1.0f);
        const float c1 = (1.0f - gc) * lambd[0];

        const uint32_t hb = (uint32_t)__cvta_generic_to_shared(hs);
        const uint32_t qoffH = (uint32_t)(q * 68 * 4);

        if (s < HH) hs[(s >> 6) * 68 + (s & 63)] = 0.0f;
        float hprev = 0.0f;
        BAR_SYNC(1, 256);

        for (int ch = 0; ch < NCH; ch++) {
            const int p = ch & 1;
            BAR_SYNC(2 + p, 512);             // xw[p] ready
            const float* xwb = xw_s + (size_t)p * CH * HH + c;
#pragma unroll
            for (int d = 0; d < CH; d++) {
                const int t = ch * CH + d;
                const float xwv = xwb[d * HH];
                const uint32_t ra = hb + ((t & 1) ? 544u : 0u) + qoffH;
                ull z0 = packf2(0.f, 0.f);
                ull a0 = z0, a1 = z0, a2 = z0, a3 = z0;
#pragma unroll
                for (int i = 0; i < 8; i++) {
                    ull p0, p1, p2, p3;
                    lds_v2u64(p0, p1, ra + (uint32_t)(i * 32));
                    lds_v2u64(p2, p3, ra + (uint32_t)(i * 32 + 16));
                    a0 = ffma2(p0, ureg[4 * i],     a0);
                    a1 = ffma2(p1, ureg[4 * i + 1], a1);
                    a2 = ffma2(p2, ureg[4 * i + 2], a2);
                    a3 = ffma2(p3, ureg[4 * i + 3], a3);
                }
                ull sacc = addf2(addf2(a0, a1), addf2(a2, a3));
                float2 f = unpackf2(sacc);
                float part = f.x + f.y;
                float pre = part + __shfl_xor_sync(0xffffffffu, part, 16) + xwv;

                float zz = sigmoidf_(pre + bgj);
                float hh = tanhf_(pre + buj);
                float hn = zz * hprev + (sz * (1.0f - zz) + sn) * hh;
                float hc = gc * hn + c1;

                if (lane < 16) {
                    hs[((t & 1) ^ 1) * 136 + (c >> 6) * 68 + (c & 63)] = hc;
                    outp[(size_t)t * HH + c] = hc;
                }
                hprev = hc;
                BAR_SYNC(1, 256);
            }
            if (PROD) {
                __threadfence();
                BAR_SYNC(1, 256);
                if (s == 0) st_release(flagRel, (unsigned)((ch + 1) * CH));
            }
            BAR_ARRIVE(4 + p, 512);           // xw[p] free
        }
        if (lane < 16) hl[c] = hprev;
    } else {
        // ---------------- PROJ (low wids) ----------------
        const int t2  = tid;
        const int wp2 = t2 >> 5;
        const int qp  = lane >> 4;
        const int cp  = wp2 * 16 + (lane & 15);

        ull wreg[16];
#pragma unroll
        for (int m = 0; m < 16; m++) {
            int k0 = C0 + 32 * qp + 2 * m;
            wreg[m] = packf2(w[(size_t)k0 * HH + cp], w[(size_t)(k0 + 1) * HH + cp]);
        }

        const int rowd = t2 >> 4;            // 0..7 (t2 < 128)
        const int e    = (t2 & 15) * 4;      // 0..60
        const int eq   = e >> 5, ew = e & 31;
        const uint32_t xb = (uint32_t)__cvta_generic_to_shared(xt);

        for (int ch = 0; ch < NCH; ch++) {
            const int p = ch & 1;
            if (!PROD) {
                while (ld_acquire(flagWait) < (unsigned)((ch + 1) * CH)) { }
            }
            float4 sreg = make_float4(0.f, 0.f, 0.f, 0.f);
            if (t2 < 128)
                sreg = __ldcg(reinterpret_cast<const float4*>(
                    xsrc + (size_t)(ch * CH + rowd) * STRIDE + C0 + e));
            float xp[CH];
#pragma unroll
            for (int d = 0; d < CH; d++) xp[d] = 0.0f;
            if (!PROD && lane < 16) {
#pragma unroll
                for (int d = 0; d < CH; d++)
                    xp[d] = __ldcg(xw1p + (size_t)(ch * CH + d) * HH + cp);
            }
            if (ch >= 2) BAR_SYNC(4 + p, 512);   // xw[p] free again
            if (t2 < 128)
                *reinterpret_cast<float4*>(
                    &xt[p * XTS + rowd * XROW + eq * 36 + ew]) = sreg;
            BAR_SYNC(7, 256);                    // staging done (proj-internal)

            const uint32_t tb = xb + (uint32_t)(p * XTS * 4) + (uint32_t)(qp * 36 * 4);
#pragma unroll
            for (int d = 0; d < CH; d++) {
                ull b0 = packf2(0.f, 0.f), b1 = b0;
                const uint32_t base = tb + (uint32_t)(d * XROW * 4);
#pragma unroll
                for (int i = 0; i < 4; i++) {
                    ull p0, p1, p2, p3;
                    lds_v2u64(p0, p1, base + (uint32_t)(i * 32));
                    lds_v2u64(p2, p3, base + (uint32_t)(i * 32 + 16));
                    b0 = ffma2(p0, wreg[4 * i],     b0);
                    b1 = ffma2(p1, wreg[4 * i + 1], b1);
                    b0 = ffma2(p2, wreg[4 * i + 2], b0);
                    b1 = ffma2(p3, wreg[4 * i + 3], b1);
                }
                float2 f0 = unpackf2(addf2(b0, b1));
                float pp = f0.x + f0.y;
                pp += __shfl_xor_sync(0xffffffffu, pp, 16);
                if (lane < 16) xw_s[(size_t)(p * CH + d) * HH + cp] = pp + xp[d];
            }
            BAR_ARRIVE(2 + p, 512);              // xw[p] ready
        }
    }
}

// ================= Helper CTA: partial xw1 over k in [0,64) =================
// 512 threads, 4-way k-split of 64: thread (q,c): q=lane>>3, c=warp*8+(lane&7).
// Per chunk per owned batch: stage 8 rows x 64 cols, dot vs w1[0:64,:], write
// g_xw1p, release flagH. Next batch's rows prefetched during the dot.
__device__ __forceinline__ void helper_cta(
    float* ht, const float* __restrict__ w1, int base, int cnt)
{
    const int tid  = threadIdx.x;
    const int lane = tid & 31;
    const int wp   = tid >> 5;
    const int q    = lane >> 3;
    const int c    = wp * 8 + (lane & 7);

    ull wreg[8];
#pragma unroll
    for (int m = 0; m < 8; m++) {
        int k0 = 16 * q + 2 * m;
        wreg[m] = packf2(w1[(size_t)k0 * HH + c], w1[(size_t)(k0 + 1) * HH + c]);
    }
    const uint32_t hbb = (uint32_t)__cvta_generic_to_shared(ht);
    const int rowd = tid >> 4;           // 0..7  (tid < 128)
    const int e    = (tid & 15) * 4;     // 0..60
    const int eq   = e >> 4, ew = e & 15;

    // prologue prefetch: (ch=0, j=0)
    float4 sreg = make_float4(0.f, 0.f, 0.f, 0.f);
    if (tid < 128) {
        while (ld_acquire(&g_flagP[base]) < CH) { }
        sreg = __ldcg(reinterpret_cast<const float4*>(
            g_seq0 + (size_t)base * SS * HH + (size_t)rowd * HH + e));
    }

    for (int ch = 0; ch < NCH; ch++) {
        for (int j = 0; j < cnt; j++) {
            const int b = base + j;
            if (tid < 128)
                *reinterpret_cast<float4*>(&ht[rowd * 80 + eq * 20 + ew]) = sreg;
            __syncthreads();
            // prefetch next (b, ch) in sequence
            {
                int nj = j + 1, nch = ch;
                if (nj == cnt) { nj = 0; nch = ch + 1; }
                if (nch < NCH && tid < 128) {
                    const int nb = base + nj;
                    while (ld_acquire(&g_flagP[nb]) < (unsigned)((nch + 1) * CH)) { }
                    sreg = __ldcg(reinterpret_cast<const float4*>(
                        g_seq0 + (size_t)nb * SS * HH +
                        (size_t)(nch * CH + rowd) * HH + e));
                }
            }
            float* outb = g_xw1p + (size_t)b * SS * HH;
#pragma unroll
            for (int d = 0; d < CH; d++) {
                const uint32_t bse = hbb + (uint32_t)(d * 80 * 4) + (uint32_t)(q * 20 * 4);
                ull b0 = packf2(0.f, 0.f), b1 = b0;
#pragma unroll
                for (int i = 0; i < 4; i++) {
                    ull p0, p1;
                    lds_v2u64(p0, p1, bse + (uint32_t)(i * 16));
                    b0 = ffma2(p0, wreg[2 * i], b0);
                    b1 = ffma2(p1, wreg[2 * i + 1], b1);
                }
                float2 f = unpackf2(addf2(b0, b1));
                float pp = f.x + f.y;
                pp += __shfl_xor_sync(0xffffffffu, pp, 8);
                pp += __shfl_xor_sync(0xffffffffu, pp, 16);
                if (lane < 8) outb[(size_t)(ch * CH + d) * HH + c] = pp;
            }
            __threadfence();
            __syncthreads();
            if (tid == 0) st_release(&g_flagH[b], (unsigned)((ch + 1) * CH));
        }
    }
}

// ================= fused persistent kernel: 64 P + 64 C + 20 helpers ==========
__global__ void __launch_bounds__(512, 1) fused_grnn(
    const float* __restrict__ x,
    const float* __restrict__ u0, const float* __restrict__ w0,
    const float* __restrict__ bg0, const float* __restrict__ bu0,
    const float* __restrict__ zeta0, const float* __restrict__ nu0,
    const float* __restrict__ lambd0, const float* __restrict__ gamma0,
    const float* __restrict__ u1, const float* __restrict__ w1,
    const float* __restrict__ bg1, const float* __restrict__ bu1,
    const float* __restrict__ zeta1, const float* __restrict__ nu1,
    const float* __restrict__ lambd1, const float* __restrict__ gamma1,
    float* __restrict__ out1, float* __restrict__ hn)
{
    __shared__ __align__(16) float hs[2 * 136];
    __shared__ __align__(16) float xt[2 * CH * 72];
    __shared__ __align__(16) float xw_s[2 * CH * HH];
    __shared__ __align__(16) float ht[CH * 80];

    const int rank = blockIdx.x;
    if (rank < BB) {
        const int b = rank;
        scan_cta<II, 0, true>(hs, xt, xw_s,
            x + (size_t)b * SS * II, u0, w0,
            bg0, bu0, zeta0, nu0, lambd0, gamma0,
            nullptr,
            g_seq0 + (size_t)b * SS * HH,
            hn + (size_t)b * HH,
            &g_flagP[b], nullptr);
    } else if (rank < 2 * BB) {
        const int b = rank - BB;
        scan_cta<HH, 64, false>(hs, xt, xw_s,
            g_seq0 + (size_t)b * SS * HH, u1, w1,
            bg1, bu1, zeta1, nu1, lambd1, gamma1,
            g_xw1p + (size_t)b * SS * HH,
            out1 + (size_t)b * SS * HH,
            hn + (size_t)(BB + b) * HH,
            nullptr, &g_flagH[b]);
    } else {
        const int i = rank - 2 * BB;               // 0..19
        const int base = (i < 4) ? 4 * i : 16 + 3 * (i - 4);
        const int cnt  = (i < 4) ? 4 : 3;
        helper_cta(ht, w1, base, cnt);
    }
}

// ---------------- launch ----------------
extern "C" void kernel_launch(void* const* d_in, const int* in_sizes, int n_in,
                              void* d_out, int out_size)
{
    const float* x      = (const float*)d_in[0];
    const float* w0     = (const float*)d_in[1];
    const float* u0     = (const float*)d_in[2];
    const float* bg0    = (const float*)d_in[3];
    const float* bu0    = (const float*)d_in[4];
    const float* zeta0  = (const float*)d_in[5];
    const float* nu0    = (const float*)d_in[6];
    const float* lambd0 = (const float*)d_in[7];
    const float* gamma0 = (const float*)d_in[8];
    const float* w1     = (const float*)d_in[9];
    const float* u1     = (const float*)d_in[10];
    const float* bg1    = (const float*)d_in[11];
    const float* bu1    = (const float*)d_in[12];
    const float* zeta1  = (const float*)d_in[13];
    const float* nu1    = (const float*)d_in[14];
    const float* lambd1 = (const float*)d_in[15];
    const float* gamma1 = (const float*)d_in[16];

    float* out1 = (float*)d_out;                          // [B,S,H]
    float* hn   = out1 + (size_t)BB * SS * HH;            // [2,B,H]

    zero_flags<<<1, 128>>>();
    fused_grnn<<<2 * BB + NHELP, 512>>>(x,
        u0, w0, bg0, bu0, zeta0, nu0, lambd0, gamma0,
        u1, w1, bg1, bu1, zeta1, nu1, lambd1, gamma1,
        out1, hn);
}

// round 10
// speedup vs baseline: 2.0885x; 2.0885x over previous
#include <cuda_runtime.h>
#include <cstdint>

#define BB 64
#define SS 2048
#define II 64
#define HH 128
#define CH 16
#define NCH (SS/CH)
#define MROWS (BB*SS)

typedef unsigned long long ull;

// Scratch + inter-CTA progress flags (no runtime allocation allowed).
__device__ __align__(256) float g_seq0[(size_t)MROWS * HH];
__device__ unsigned g_flag[BB];

#define BAR_SYNC(id, cnt)   asm volatile("bar.sync %0, %1;"   :: "r"(id), "r"(cnt) : "memory")
#define BAR_ARRIVE(id, cnt) asm volatile("bar.arrive %0, %1;" :: "r"(id), "r"(cnt) : "memory")

// ---------------- packed f32x2 helpers (sm_100+) ----------------
__device__ __forceinline__ ull packf2(float lo, float hi) {
    ull r; asm("mov.b64 %0, {%1, %2};" : "=l"(r) : "f"(lo), "f"(hi)); return r;
}
__device__ __forceinline__ float2 unpackf2(ull v) {
    float2 r; asm("mov.b64 {%0, %1}, %2;" : "=f"(r.x), "=f"(r.y) : "l"(v)); return r;
}
__device__ __forceinline__ ull ffma2(ull a, ull b, ull c) {
    ull d; asm("fma.rn.f32x2 %0, %1, %2, %3;" : "=l"(d) : "l"(a), "l"(b), "l"(c)); return d;
}
__device__ __forceinline__ ull addf2(ull a, ull b) {
    ull d; asm("add.rn.f32x2 %0, %1, %2;" : "=l"(d) : "l"(a), "l"(b)); return d;
}
__device__ __forceinline__ void lds_v2u64(ull &p0, ull &p1, uint32_t addr) {
    asm volatile("ld.shared.v2.u64 {%0, %1}, [%2];" : "=l"(p0), "=l"(p1) : "r"(addr));
}
__device__ __forceinline__ float ex2f(float x) {
    float r; asm("ex2.approx.ftz.f32 %0, %1;" : "=f"(r) : "f"(x)); return r;
}
__device__ __forceinline__ float rcpf(float x) {
    float r; asm("rcp.approx.ftz.f32 %0, %1;" : "=f"(r) : "f"(x)); return r;
}
__device__ __forceinline__ float sigmoidf_(float x) {
    return rcpf(1.0f + ex2f(-1.4426950408889634f * x));
}
__device__ __forceinline__ unsigned ld_acquire(const unsigned* p) {
    unsigned v;
    asm volatile("ld.acquire.gpu.global.u32 %0, [%1];" : "=r"(v) : "l"(p) : "memory");
    return v;
}
__device__ __forceinline__ void st_release(unsigned* p, unsigned v) {
    asm volatile("st.release.gpu.global.u32 [%0], %1;" :: "l"(p), "r"(v) : "memory");
}

__global__ void zero_flags() {
    if (threadIdx.x < BB) g_flag[threadIdx.x] = 0;
}

// ---------------- warp-specialized role (scan on HIGH wids) ----------------
// CTA = one (layer, batch), 512 threads.
//  tid >= 256: SCAN warps (high wid -> arbiter priority). Thread (q,c):
//      q=lane>>4 (k-half), c=warp*16+(lane&15). ureg = u[64q:64q+64, c].
//      Per step: 16 LDS.128 + 32 ffma2 (4 chains), shfl-reduce halves, gates
//      (fma-form args, shared-term algebra), h double-buffer, bar 1 (256).
//  tid <  256: PROJ warps. 2-way k-split of W; stage CH input rows into
//      double-buffered xt, compute xw chunk into double-buffered xw_s.
//      Consumer: ONLY thread 0 spins on the producer flag, then bar 7 fans out.
// Handshake: bar 2+p = xw[p] ready (proj arrive / scan sync);
//            bar 4+p = xw[p] free (scan arrive / proj sync, from ch>=2).
template<int KF, bool PROD>
__device__ __forceinline__ void role(
    float* hs, float* xt, float* xw_s,
    const float* __restrict__ xsrc,   // rows of width KF
    const float* __restrict__ u,      // [H,H]
    const float* __restrict__ w,      // [KF,H]
    const float* bg, const float* bu,
    const float* zeta, const float* nu,
    const float* lambd, const float* gamma,
    float* __restrict__ outp,         // [S,H] slice
    float* __restrict__ hl,           // [H] slice
    unsigned* flagRel, const unsigned* flagWait)
{
    constexpr int KH   = KF / 2;         // per-thread k-values (32 or 64)
    constexpr int KHP  = KH + 4;         // padded half width
    constexpr int XROW = 2 * KHP;        // staged row stride (72 or 136)
    constexpr int XTS  = CH * XROW;      // xt buffer stride
    constexpr int CPR  = KF / 4;         // float4s per row (16 or 32)
    constexpr int RPP  = 256 / CPR;      // rows per load pass (16 or 8)
    constexpr int LPT  = CH / RPP;       // load passes (1 or 2)

    const int tid  = threadIdx.x;
    const int lane = tid & 31;

    if (tid >= 256) {
        // ================= SCAN (high wids) =================
        const int s  = tid - 256;
        const int wp = s >> 5;
        const int q  = lane >> 4;
        const int c  = wp * 16 + (lane & 15);

        ull ureg[32];
#pragma unroll
        for (int m = 0; m < 32; m++) {
            int k0 = 64 * q + 2 * m;
            ureg[m] = packf2(u[(size_t)k0 * HH + c], u[(size_t)(k0 + 1) * HH + c]);
        }
        const float sz = sigmoidf_(zeta[0]);
        const float sn = sigmoidf_(nu[0]);
        float gc = gamma[0];
        gc = fminf(fmaxf(gc, 0.0f), 1.0f);
        const float c1   = (1.0f - gc) * lambd[0];
        const float szsn = sz + sn;
        const float bgs  = -1.4426950408889634f * bg[c];
        const float bus  =  2.8853900817779268f * bu[c];

        const uint32_t hb = (uint32_t)__cvta_generic_to_shared(hs);
        const uint32_t qoffH = (uint32_t)(q * 68 * 4);

        if (s < HH) hs[(s >> 6) * 68 + (s & 63)] = 0.0f;
        float hprev = 0.0f;
        BAR_SYNC(1, 256);

        for (int ch = 0; ch < NCH; ch++) {
            const int p = ch & 1;
            BAR_SYNC(2 + p, 512);                 // xw[p] ready
            float xwv[CH];
            const float* xwb = xw_s + (size_t)p * CH * HH + c;
#pragma unroll
            for (int d = 0; d < CH; d++) xwv[d] = xwb[d * HH];
#pragma unroll
            for (int d = 0; d < CH; d++) {
                const int t = ch * CH + d;
                const uint32_t ra = hb + ((t & 1) ? 544u : 0u) + qoffH;
                ull z0 = packf2(0.f, 0.f);
                ull a0 = z0, a1 = z0, a2 = z0, a3 = z0;
#pragma unroll
                for (int i = 0; i < 8; i++) {
                    ull p0, p1, p2, p3;
                    lds_v2u64(p0, p1, ra + (uint32_t)(i * 32));
                    lds_v2u64(p2, p3, ra + (uint32_t)(i * 32 + 16));
                    a0 = ffma2(p0, ureg[4 * i],     a0);
                    a1 = ffma2(p1, ureg[4 * i + 1], a1);
                    a2 = ffma2(p2, ureg[4 * i + 2], a2);
                    a3 = ffma2(p3, ureg[4 * i + 3], a3);
                }
                float2 f = unpackf2(addf2(addf2(a0, a1), addf2(a2, a3)));
                float part = f.x + f.y;
                float pre = part + __shfl_xor_sync(0xffffffffu, part, 16) + xwv[d];

                float z  = rcpf(1.0f + ex2f(fmaf(-1.4426950408889634f, pre, bgs)));
                float hh = 1.0f - 2.0f * rcpf(1.0f + ex2f(fmaf(2.8853900817779268f, pre, bus)));
                float t1 = fmaf(-sz, hh, hprev);          // hprev - sz*hh
                float hn = fmaf(z, t1, szsn * hh);        // z*(h - sz*hh) + (sz+sn)*hh
                float hc = fmaf(gc, hn, c1);

                if (lane < 16) {
                    hs[((t & 1) ^ 1) * 136 + (c >> 6) * 68 + (c & 63)] = hc;
                    outp[(size_t)t * HH + c] = hc;
                }
                hprev = hc;
                BAR_SYNC(1, 256);
            }
            if (PROD) {
                __threadfence();
                BAR_SYNC(1, 256);
                if (s == 0) st_release(flagRel, (unsigned)((ch + 1) * CH));
            }
            BAR_ARRIVE(4 + p, 512);               // xw[p] free
        }
        if (lane < 16) hl[c] = hprev;
    } else {
        // ================= PROJ (low wids) =================
        const int wp2 = tid >> 5;
        const int qp  = lane >> 4;
        const int cp  = wp2 * 16 + (lane & 15);

        ull wreg[KH / 2];
#pragma unroll
        for (int m = 0; m < KH / 2; m++) {
            int k0 = KH * qp + 2 * m;
            wreg[m] = packf2(w[(size_t)k0 * HH + cp], w[(size_t)(k0 + 1) * HH + cp]);
        }

        const int rowd = tid / CPR;          // row within a pass
        const int e    = (tid % CPR) * 4;    // float column within row
        const int eq   = e / KH, ew = e % KH;
        const uint32_t xb = (uint32_t)__cvta_generic_to_shared(xt);

        for (int ch = 0; ch < NCH; ch++) {
            const int p = ch & 1;
            if (!PROD) {
                if (tid == 0) {
                    while (ld_acquire(flagWait) < (unsigned)((ch + 1) * CH)) { }
                }
                BAR_SYNC(7, 256);            // flag visibility fan-out
            }
            float4 sreg[LPT];
#pragma unroll
            for (int l = 0; l < LPT; l++)
                sreg[l] = __ldcg(reinterpret_cast<const float4*>(
                    xsrc + (size_t)(ch * CH + l * RPP + rowd) * KF + e));
            if (ch >= 2) BAR_SYNC(4 + p, 512);   // xw[p] free again
#pragma unroll
            for (int l = 0; l < LPT; l++)
                *reinterpret_cast<float4*>(
                    &xt[p * XTS + (l * RPP + rowd) * XROW + eq * KHP + ew]) = sreg[l];
            BAR_SYNC(7, 256);                    // staging done

            const uint32_t tb = xb + (uint32_t)(p * XTS * 4) + (uint32_t)(qp * KHP * 4);
#pragma unroll
            for (int d = 0; d < CH; d++) {
                const uint32_t base = tb + (uint32_t)(d * XROW * 4);
                ull z0 = packf2(0.f, 0.f);
                ull b0 = z0, b1 = z0, b2 = z0, b3 = z0;
#pragma unroll
                for (int i = 0; i < KH / 8; i++) {
                    ull p0, p1, p2, p3;
                    lds_v2u64(p0, p1, base + (uint32_t)(i * 32));
                    lds_v2u64(p2, p3, base + (uint32_t)(i * 32 + 16));
                    b0 = ffma2(p0, wreg[4 * i],     b0);
                    b1 = ffma2(p1, wreg[4 * i + 1], b1);
                    b2 = ffma2(p2, wreg[4 * i + 2], b2);
                    b3 = ffma2(p3, wreg[4 * i + 3], b3);
                }
                float2 f = unpackf2(addf2(addf2(b0, b1), addf2(b2, b3)));
                float pp = f.x + f.y;
                pp += __shfl_xor_sync(0xffffffffu, pp, 16);
                if (lane < 16) xw_s[(size_t)(p * CH + d) * HH + cp] = pp;
            }
            BAR_ARRIVE(2 + p, 512);              // xw[p] ready
        }
    }
}

// ---------------- fused persistent kernel: 64 producer + 64 consumer CTAs
__global__ void __launch_bounds__(512, 1) fused_grnn(
    const float* __restrict__ x,
    const float* __restrict__ u0, const float* __restrict__ w0,
    const float* __restrict__ bg0, const float* __restrict__ bu0,
    const float* __restrict__ zeta0, const float* __restrict__ nu0,
    const float* __restrict__ lambd0, const float* __restrict__ gamma0,
    const float* __restrict__ u1, const float* __restrict__ w1,
    const float* __restrict__ bg1, const float* __restrict__ bu1,
    const float* __restrict__ zeta1, const float* __restrict__ nu1,
    const float* __restrict__ lambd1, const float* __restrict__ gamma1,
    float* __restrict__ out1, float* __restrict__ hn)
{
    __shared__ __align__(16) float hs[2 * 136];
    __shared__ __align__(16) float xt[2 * CH * 136];    // sized for KF=128
    __shared__ __align__(16) float xw_s[2 * CH * HH];

    const int rank = blockIdx.x;
    if (rank < BB) {
        const int b = rank;
        role<II, true>(hs, xt, xw_s,
            x + (size_t)b * SS * II, u0, w0,
            bg0, bu0, zeta0, nu0, lambd0, gamma0,
            g_seq0 + (size_t)b * SS * HH,
            hn + (size_t)b * HH,
            &g_flag[b], nullptr);
    } else {
        const int b = rank - BB;
        role<HH, false>(hs, xt, xw_s,
            g_seq0 + (size_t)b * SS * HH, u1, w1,
            bg1, bu1, zeta1, nu1, lambd1, gamma1,
            out1 + (size_t)b * SS * HH,
            hn + (size_t)(BB + b) * HH,
            nullptr, &g_flag[b]);
    }
}

// ---------------- launch ----------------
extern "C" void kernel_launch(void* const* d_in, const int* in_sizes, int n_in,
                              void* d_out, int out_size)
{
    const float* x      = (const float*)d_in[0];
    const float* w0     = (const float*)d_in[1];
    const float* u0     = (const float*)d_in[2];
    const float* bg0    = (const float*)d_in[3];
    const float* bu0    = (const float*)d_in[4];
    const float* zeta0  = (const float*)d_in[5];
    const float* nu0    = (const float*)d_in[6];
    const float* lambd0 = (const float*)d_in[7];
    const float* gamma0 = (const float*)d_in[8];
    const float* w1     = (const float*)d_in[9];
    const float* u1     = (const float*)d_in[10];
    const float* bg1    = (const float*)d_in[11];
    const float* bu1    = (const float*)d_in[12];
    const float* zeta1  = (const float*)d_in[13];
    const float* nu1    = (const float*)d_in[14];
    const float* lambd1 = (const float*)d_in[15];
    const float* gamma1 = (const float*)d_in[16];

    float* out1 = (float*)d_out;                          // [B,S,H]
    float* hn   = out1 + (size_t)BB * SS * HH;            // [2,B,H]

    zero_flags<<<1, 64>>>();
    fused_grnn<<<2 * BB, 512>>>(x,
        u0, w0, bg0, bu0, zeta0, nu0, lambd0, gamma0,
        u1, w1, bg1, bu1, zeta1, nu1, lambd1, gamma1,
        out1, hn);
}